// round 4
// baseline (speedup 1.0000x reference)
#include <cuda_runtime.h>

#define HID   51
#define GATES 204          // 4*HID
#define SEQ   999
#define BATCH 4096
#define BT    14           // real batch rows per block
#define BTP   16           // padded (lanes 14,15 dummy)
#define NBLK  ((BATCH + BT - 1) / BT)   // 293
#define CHUNK 111          // 999 = 9*111
#define GPAD  17           // gates row stride, coprime-ish with 32

typedef unsigned long long u64;

__device__ __forceinline__ u64 pack2(float a, float b) {
    u64 r; asm("mov.b64 %0,{%1,%2};" : "=l"(r) : "f"(a), "f"(b)); return r;
}
__device__ __forceinline__ void unpack2(float& a, float& b, u64 p) {
    asm("mov.b64 {%0,%1},%2;" : "=f"(a), "=f"(b) : "l"(p));
}
__device__ __forceinline__ u64 ffma2(u64 a, u64 b, u64 c) {
    u64 d; asm("fma.rn.f32x2 %0,%1,%2,%3;" : "=l"(d) : "l"(a), "l"(b), "l"(c)); return d;
}

__device__ __forceinline__ float sigf(float x) {
    return __fdividef(1.0f, 1.0f + __expf(-x));
}
__device__ __forceinline__ float tanh_(float x) {
    return __fdividef(2.0f, 1.0f + __expf(-2.0f * x)) - 1.0f;
}

__global__ __launch_bounds__(256, 2)
void lstm_persistent(const float* __restrict__ input,
                     const float* __restrict__ W_ih,
                     const float* __restrict__ W_hh,
                     const float* __restrict__ b_ih,
                     const float* __restrict__ b_hh,
                     const float* __restrict__ W_fc,
                     const float* __restrict__ b_fc,
                     float* __restrict__ out)
{
    __shared__ float h_sh[HID * BTP];            // TRANSPOSED: h_T[k][b], 64B rows
    __shared__ float gates_sh[GATES * GPAD];     // [gate_row][b]
    __shared__ float x_sh[BTP * CHUNK];          // input chunk (rows >= BT unread garbage)

    const int tid = threadIdx.x;
    const int b0  = blockIdx.x * BT;
    const int B_local = min(BT, BATCH - b0);     // 14, or 8 on last block

    // ---- per-thread row weights in registers ----
    float whh[HID];
    float bias = 0.0f, wih = 0.0f;
    if (tid < GATES) {
        bias = b_ih[tid] + b_hh[tid];
        wih  = W_ih[tid];                        // INPUT==1
        #pragma unroll
        for (int k = 0; k < HID; k++) whh[k] = W_hh[tid * HID + k];
    } else if (tid == GATES) {                   // fused FC row
        bias = b_fc[0];
        #pragma unroll
        for (int k = 0; k < HID; k++) whh[k] = W_fc[k];
    }

    // zero h_T (pad lanes stay 0 forever)
    for (int e = tid; e < HID * BTP; e += 256) h_sh[e] = 0.0f;

    // c-state in registers; mapping e = tid + 256*r, b = e&15 (fast), k = e>>4
    float creg[4] = {0.0f, 0.0f, 0.0f, 0.0f};

    const bool is_gate = (tid < GATES);
    const bool is_fc   = (tid == GATES);

    for (int t = 0; t <= SEQ; ++t) {
        if (t < SEQ && (t % CHUNK) == 0) {       // stage input chunk (coalesced-ish)
            int n = B_local * CHUNK;
            for (int e = tid; e < n; e += 256) {
                int b  = e / CHUNK;
                int tc = e - b * CHUNK;
                x_sh[b * CHUNK + tc] = input[(size_t)(b0 + b) * SEQ + (t + tc)];
            }
        }
        __syncthreads();   // A: h_T(t-1) and x ready

        // ---- GEMM phase: 16 batch lanes per thread via f32x2 packed FMA ----
        bool act = is_gate ? (t < SEQ) : (is_fc && t > 0);
        if (act) {
            const int tc = t % CHUNK;
            u64 acc[8];
            #pragma unroll
            for (int g = 0; g < 4; g++) {        // init: bias + wih * x_t  (wih==0 for fc)
                float a0 = fmaf(wih, x_sh[(4 * g + 0) * CHUNK + tc], bias);
                float a1 = fmaf(wih, x_sh[(4 * g + 1) * CHUNK + tc], bias);
                float a2 = fmaf(wih, x_sh[(4 * g + 2) * CHUNK + tc], bias);
                float a3 = fmaf(wih, x_sh[(4 * g + 3) * CHUNK + tc], bias);
                acc[2 * g]     = pack2(a0, a1);
                acc[2 * g + 1] = pack2(a2, a3);
            }
            #pragma unroll
            for (int k = 0; k < HID; k++) {
                u64 wp = pack2(whh[k], whh[k]);
                const ulonglong2* row =
                    reinterpret_cast<const ulonglong2*>(h_sh + k * BTP);
                ulonglong2 r0 = row[0];          // lanes 0..3   (LDS.128 broadcast)
                ulonglong2 r1 = row[1];          // lanes 4..7
                ulonglong2 r2 = row[2];          // lanes 8..11
                ulonglong2 r3 = row[3];          // lanes 12..15
                acc[0] = ffma2(r0.x, wp, acc[0]);
                acc[1] = ffma2(r0.y, wp, acc[1]);
                acc[2] = ffma2(r1.x, wp, acc[2]);
                acc[3] = ffma2(r1.y, wp, acc[3]);
                acc[4] = ffma2(r2.x, wp, acc[4]);
                acc[5] = ffma2(r2.y, wp, acc[5]);
                acc[6] = ffma2(r3.x, wp, acc[6]);
                acc[7] = ffma2(r3.y, wp, acc[7]);
            }
            if (is_gate) {
                #pragma unroll
                for (int g = 0; g < 8; g++) {
                    float lo, hi; unpack2(lo, hi, acc[g]);
                    gates_sh[tid * GPAD + 2 * g]     = lo;   // stride-17: conflict-free
                    gates_sh[tid * GPAD + 2 * g + 1] = hi;
                }
            } else {                              // fc: y_{t-1} for this block
                float y[BTP];
                #pragma unroll
                for (int g = 0; g < 8; g++) unpack2(y[2 * g], y[2 * g + 1], acc[g]);
                for (int b = 0; b < B_local; b++)
                    out[(size_t)(b0 + b) * SEQ + (t - 1)] = y[b];
            }
        }
        __syncthreads();   // B: gates ready; GEMM done reading h_T

        // ---- elementwise LSTM cell update -> h_T(t) ----
        if (t < SEQ) {
            #pragma unroll
            for (int r = 0; r < 4; r++) {
                int e = tid + 256 * r;
                if (e < HID * BTP) {
                    int b = e & 15, k = e >> 4;
                    if (b < B_local) {
                        float gi = gates_sh[(k          ) * GPAD + b];
                        float gf = gates_sh[(k +     HID) * GPAD + b];
                        float gg = gates_sh[(k + 2 * HID) * GPAD + b];
                        float go = gates_sh[(k + 3 * HID) * GPAD + b];
                        float c  = sigf(gf) * creg[r] + sigf(gi) * tanh_(gg);
                        creg[r]  = c;
                        h_sh[k * BTP + b] = sigf(go) * tanh_(c);  // conflict-free
                    }
                }
            }
        }
    }
}

extern "C" void kernel_launch(void* const* d_in, const int* in_sizes, int n_in,
                              void* d_out, int out_size) {
    const float* input = (const float*)d_in[0];
    const float* W_ih  = (const float*)d_in[1];
    const float* W_hh  = (const float*)d_in[2];
    const float* b_ih  = (const float*)d_in[3];
    const float* b_hh  = (const float*)d_in[4];
    const float* W_fc  = (const float*)d_in[5];
    const float* b_fc  = (const float*)d_in[6];
    lstm_persistent<<<NBLK, 256>>>(input, W_ih, W_hh, b_ih, b_hh, W_fc, b_fc,
                                   (float*)d_out);
}